// round 4
// baseline (speedup 1.0000x reference)
#include <cuda_runtime.h>
#include <cuda_bf16.h>

// Rotation scan: h_t = lambda * h_{t-1} + x_t  (complex), lambda = r*cos(th) - i*r*sin(th)
// x: (T, N, 2) fp32 -> float2[T][N]. Output same shape.
//
// R4: 128-bit accesses. Each thread owns NPT=2 adjacent n-channels, so every
// global access is LDG.128/STG.128 (16B/lane). Grid stays 512 (best so far).
// THREADS=128: 8 n-lane threads (x2 channels = NB 16 n) * TT=16 time-segments.

#define L   16
#define TT  16
#define NL  8              // n-lane threads per time-row
#define NPT 2              // n-channels per thread
#define NB  (NL * NPT)     // 16
#define THREADS (TT * NL)  // 128

__global__ void __launch_bounds__(THREADS)
rot_scan_kernel(const float4* __restrict__ x4,
                const float*  __restrict__ angles,
                const float*  __restrict__ rets,
                float4* __restrict__ out4,
                int T, int N)
{
    const int tid    = threadIdx.x;
    const int n_lane = tid & (NL - 1);
    const int tt     = tid / NL;                  // 0..TT-1
    const int n0     = blockIdx.x * NB + n_lane * NPT;   // first of 2 channels
    const int Nq     = N / NPT;                   // row stride in float4

    const float PI = 3.14159265358979323846f;

    // per-channel operator lambda_c = ret*cos(ang) - i*ret*sin(ang)
    float lr[NPT], li[NPT];
    float plr[NPT], pli[NPT];   // lambda^L
    float wr[NPT],  wi[NPT];    // lambda^(L*tt)
    float flr[NPT], fli[NPT];   // lambda^(L*TT)
#pragma unroll
    for (int c = 0; c < NPT; c++) {
        float ang = (tanhf(angles[n0 + c]) + 1.0f) * 0.5f * PI;
        float ret = (tanhf(rets[n0 + c])   + 1.0f) * 0.5f;
        float sn, cs;
        sincosf(ang, &sn, &cs);
        lr[c] =  ret * cs;
        li[c] = -ret * sn;

        // lambda^L (L=16): 4 squarings
        float ar = lr[c], ai = li[c];
#pragma unroll
        for (int q = 0; q < 4; q++) {
            float nr = ar * ar - ai * ai;
            float ni = 2.0f * ar * ai;
            ar = nr; ai = ni;
        }
        plr[c] = ar; pli[c] = ai;

        // lambda^(L*tt)
        float br = 1.0f, bi = 0.0f;
        for (int j = 0; j < tt; j++) {
            float nr = br * ar - bi * ai;
            float ni = br * ai + bi * ar;
            br = nr; bi = ni;
        }
        wr[c] = br; wi[c] = bi;

        // lambda^(L*TT): 4 more squarings (TT=16)
        float cr = ar, ci = ai;
#pragma unroll
        for (int q = 0; q < 4; q++) {
            float nr = cr * cr - ci * ci;
            float ni = 2.0f * cr * ci;
            cr = nr; ci = ni;
        }
        flr[c] = cr; fli[c] = ci;
    }

    __shared__ float4 sagg[TT][NL];   // both channels' aggregates packed

    float hpr[NPT] = {0.f, 0.f}, hpi[NPT] = {0.f, 0.f};   // block carry

    float4 v[L];

    const int steps  = L * TT;        // 256
    const int n_iter = T / steps;     // 16

    for (int it = 0; it < n_iter; it++) {
        const int t0 = it * steps + tt * L;
        const float4* xp = x4 + (size_t)t0 * Nq + (n0 >> 1);

        // load + local scan (zero-initialized), both channels
        float br0 = 0.f, bi0 = 0.f, br1 = 0.f, bi1 = 0.f;
#pragma unroll
        for (int i = 0; i < L; i++) {
            float4 xv = __ldcs(xp + (size_t)i * Nq);
            float nr0 = fmaf(lr[0], br0, fmaf(-li[0], bi0, xv.x));
            float ni0 = fmaf(lr[0], bi0, fmaf( li[0], br0, xv.y));
            float nr1 = fmaf(lr[1], br1, fmaf(-li[1], bi1, xv.z));
            float ni1 = fmaf(lr[1], bi1, fmaf( li[1], br1, xv.w));
            br0 = nr0; bi0 = ni0; br1 = nr1; bi1 = ni1;
            v[i] = make_float4(br0, bi0, br1, bi1);
        }
        sagg[tt][n_lane] = make_float4(br0, bi0, br1, bi1);
        __syncthreads();

        // combine aggregates: acc_j = lambda^L * acc_{j-1} + A_j
        float ar0 = 0.f, ai0 = 0.f, ar1 = 0.f, ai1 = 0.f;  // running acc
        float cr0 = 0.f, ci0 = 0.f, cr1 = 0.f, ci1 = 0.f;  // carry at j==tt
#pragma unroll
        for (int j = 0; j < TT; j++) {
            if (j == tt) { cr0 = ar0; ci0 = ai0; cr1 = ar1; ci1 = ai1; }
            float4 a = sagg[j][n_lane];
            float nr0 = fmaf(plr[0], ar0, fmaf(-pli[0], ai0, a.x));
            float ni0 = fmaf(plr[0], ai0, fmaf( pli[0], ar0, a.y));
            float nr1 = fmaf(plr[1], ar1, fmaf(-pli[1], ai1, a.z));
            float ni1 = fmaf(plr[1], ai1, fmaf( pli[1], ar1, a.w));
            ar0 = nr0; ai0 = ni0; ar1 = nr1; ai1 = ni1;
        }
        __syncthreads();   // protect smem before next iteration's writes

        // total carry-in: lambda^(L*tt) * h_prev + I_{tt-1}
        float tr0 = fmaf(wr[0], hpr[0], fmaf(-wi[0], hpi[0], cr0));
        float ti0 = fmaf(wr[0], hpi[0], fmaf( wi[0], hpr[0], ci0));
        float tr1 = fmaf(wr[1], hpr[1], fmaf(-wi[1], hpi[1], cr1));
        float ti1 = fmaf(wr[1], hpi[1], fmaf( wi[1], hpr[1], ci1));

        // outputs: out_i = v_i + lambda^(i+1) * carry
        float4* op = out4 + (size_t)t0 * Nq + (n0 >> 1);
        float qr0 = fmaf(lr[0], tr0, -li[0] * ti0);
        float qi0 = fmaf(lr[0], ti0,  li[0] * tr0);
        float qr1 = fmaf(lr[1], tr1, -li[1] * ti1);
        float qi1 = fmaf(lr[1], ti1,  li[1] * tr1);
#pragma unroll
        for (int i = 0; i < L; i++) {
            float4 o;
            o.x = v[i].x + qr0;
            o.y = v[i].y + qi0;
            o.z = v[i].z + qr1;
            o.w = v[i].w + qi1;
            __stcs(op + (size_t)i * Nq, o);
            float nr0 = fmaf(lr[0], qr0, -li[0] * qi0);
            float ni0 = fmaf(lr[0], qi0,  li[0] * qr0);
            float nr1 = fmaf(lr[1], qr1, -li[1] * qi1);
            float ni1 = fmaf(lr[1], qi1,  li[1] * qr1);
            qr0 = nr0; qi0 = ni0; qr1 = nr1; qi1 = ni1;
        }

        // advance block carry: h_prev = lambda^(L*TT) * h_prev + I_{TT-1}
        float nh0r = fmaf(flr[0], hpr[0], fmaf(-fli[0], hpi[0], ar0));
        float nh0i = fmaf(flr[0], hpi[0], fmaf( fli[0], hpr[0], ai0));
        float nh1r = fmaf(flr[1], hpr[1], fmaf(-fli[1], hpi[1], ar1));
        float nh1i = fmaf(flr[1], hpi[1], fmaf( fli[1], hpr[1], ai1));
        hpr[0] = nh0r; hpi[0] = nh0i; hpr[1] = nh1r; hpi[1] = nh1i;
    }
}

extern "C" void kernel_launch(void* const* d_in, const int* in_sizes, int n_in,
                              void* d_out, int out_size)
{
    const float4* x    = (const float4*)d_in[0];
    const float*  angs = (const float*)d_in[1];
    const float*  rts  = (const float*)d_in[2];
    float4* out = (float4*)d_out;

    const int N = in_sizes[1];                       // 8192
    const int T = in_sizes[0] / (2 * N);             // 4096

    const int grid = N / NB;                         // 512 blocks
    rot_scan_kernel<<<grid, THREADS>>>(x, angs, rts, out, T, N);
}

// round 5
// speedup vs baseline: 1.1908x; 1.1908x over previous
#include <cuda_runtime.h>
#include <cuda_bf16.h>

// Rotation scan: h_t = lambda * h_{t-1} + x_t  (complex), lambda = r*cos(th) - i*r*sin(th)
// x: (T, N, 2) fp32 -> float2[T][N]. Output same shape.
//
// R5: R1 shape (NB=16, TT=8, L=16, grid=512, block=128 — best measured) plus:
//  - software pipeline: prefetch next iteration's 16 raw loads after the
//    combine, so the read stream stays in flight through the store phase
//  - double-buffered sagg -> one __syncthreads per 128-step iteration
// No cache hints (R1 baseline had none; keep one variable controlled).

#define L  16
#define TT 8
#define NB 16
#define THREADS (TT * NB)   // 128

__global__ void __launch_bounds__(THREADS)
rot_scan_kernel(const float2* __restrict__ x,
                const float*  __restrict__ angles,
                const float*  __restrict__ rets,
                float2* __restrict__ out,
                int T, int N)
{
    const int tid     = threadIdx.x;
    const int n_local = tid & (NB - 1);   // n fastest -> coalesced gmem
    const int tt      = tid / NB;         // 0..TT-1
    const int n       = blockIdx.x * NB + n_local;

    // ---- per-n operator: lambda = ret*cos(ang) - i*ret*sin(ang) ----
    const float PI = 3.14159265358979323846f;
    float ang = (tanhf(angles[n]) + 1.0f) * 0.5f * PI;   // (0, pi)
    float ret = (tanhf(rets[n])   + 1.0f) * 0.5f;        // (0, 1)
    float sn, cs;
    sincosf(ang, &sn, &cs);
    const float lr =  ret * cs;
    const float li = -ret * sn;

    // lambda^L (L=16): 4 complex squarings
    float plr = lr, pli = li;
#pragma unroll
    for (int q = 0; q < 4; q++) {
        float nr = plr * plr - pli * pli;
        float ni = 2.0f * plr * pli;
        plr = nr; pli = ni;
    }
    // lambda^(L*tt): thread-specific weight for block-carry
    float wr = 1.0f, wi = 0.0f;
    for (int j = 0; j < tt; j++) {
        float nr = wr * plr - wi * pli;
        float ni = wr * pli + wi * plr;
        wr = nr; wi = ni;
    }
    // lambda^(L*TT) = (lambda^L)^8: 3 squarings
    float flr = plr, fli = pli;
#pragma unroll
    for (int q = 0; q < 3; q++) {
        float nr = flr * flr - fli * fli;
        float ni = 2.0f * flr * fli;
        flr = nr; fli = ni;
    }

    __shared__ float2 sagg[2][TT][NB];   // double buffer -> 1 sync/iter

    float hpr = 0.0f, hpi = 0.0f;   // running carry

    float2 xv[L];   // raw prefetched inputs for current iteration
    float2 v[L];    // locally scanned values

    const int steps  = L * TT;       // 128
    const int n_iter = T / steps;

    // prologue: prefetch iteration 0
    {
        const float2* xp = x + (size_t)(tt * L) * N + n;
#pragma unroll
        for (int i = 0; i < L; i++)
            xv[i] = xp[(size_t)i * N];
    }

    for (int it = 0; it < n_iter; it++) {
        const int buf = it & 1;
        const int t0  = it * steps + tt * L;

        // local scan of prefetched values (zero-initialized)
        float br = 0.0f, bi = 0.0f;
#pragma unroll
        for (int i = 0; i < L; i++) {
            float nr = fmaf(lr, br, fmaf(-li, bi, xv[i].x));
            float ni = fmaf(lr, bi, fmaf( li, br, xv[i].y));
            br = nr; bi = ni;
            v[i].x = br; v[i].y = bi;
        }
        sagg[buf][tt][n_local] = make_float2(br, bi);
        __syncthreads();

        // combine aggregates: acc_j = lambda^L * acc_{j-1} + A_j
        float accr = 0.0f, acci = 0.0f;
        float carr = 0.0f, cari = 0.0f;
#pragma unroll
        for (int j = 0; j < TT; j++) {
            if (j == tt) { carr = accr; cari = acci; }
            float2 a = sagg[buf][j][n_local];
            float nr = fmaf(plr, accr, fmaf(-pli, acci, a.x));
            float ni = fmaf(plr, acci, fmaf( pli, accr, a.y));
            accr = nr; acci = ni;
        }
        // no second sync: next iteration writes the other buffer, and its
        // write is preceded by that iteration's __syncthreads.

        // prefetch next iteration NOW, so reads overlap the store phase
        if (it + 1 < n_iter) {
            const float2* xq = x + (size_t)((it + 1) * steps + tt * L) * N + n;
#pragma unroll
            for (int i = 0; i < L; i++)
                xv[i] = xq[(size_t)i * N];
        }

        // total carry-in for this thread = lambda^(L*tt) * h_prev + I_{tt-1}
        float cr = fmaf(wr, hpr, fmaf(-wi, hpi, carr));
        float ci = fmaf(wr, hpi, fmaf( wi, hpr, cari));

        // outputs: out_i = v_i + lambda^(i+1) * carry
        float2* op = out + (size_t)t0 * N + n;
        float qr = fmaf(lr, cr, -li * ci);
        float qi = fmaf(lr, ci,  li * cr);
#pragma unroll
        for (int i = 0; i < L; i++) {
            float2 o;
            o.x = v[i].x + qr;
            o.y = v[i].y + qi;
            op[(size_t)i * N] = o;
            float nr = fmaf(lr, qr, -li * qi);
            float ni = fmaf(lr, qi,  li * qr);
            qr = nr; qi = ni;
        }

        // advance block carry: h_prev = lambda^(L*TT) * h_prev + I_{TT-1}
        float nhr = fmaf(flr, hpr, fmaf(-fli, hpi, accr));
        float nhi = fmaf(flr, hpi, fmaf( fli, hpr, acci));
        hpr = nhr; hpi = nhi;
    }
}

extern "C" void kernel_launch(void* const* d_in, const int* in_sizes, int n_in,
                              void* d_out, int out_size)
{
    const float2* x    = (const float2*)d_in[0];
    const float*  angs = (const float*)d_in[1];
    const float*  rts  = (const float*)d_in[2];
    float2* out = (float2*)d_out;

    const int N = in_sizes[1];                       // 8192
    const int T = in_sizes[0] / (2 * N);             // 4096

    const int grid = N / NB;                         // 512 blocks
    rot_scan_kernel<<<grid, THREADS>>>(x, angs, rts, out, T, N);
}